// round 10
// baseline (speedup 1.0000x reference)
#include <cuda_runtime.h>

typedef unsigned long long u64;

#define NP 64
#define NCOLS 500000
#define BCOLS 256
#define NB    ((NCOLS + BCOLS - 1) / BCOLS)   /* 1954 gemm blocks */
#define NANG 2016
#define NSEG  8
#define SEGL  (NANG / NSEG)                   /* 252 rotations per segment */
#define KCH   16                              /* K rows per staged chunk */
#define NCH   (NP / KCH)                      /* 4 chunks */

// RT[k*64 + i] = mus[i] * R[i][k]
__device__ float d_RT[NP * NP];
// segment products, column-major: d_SEG[b*4096 + j*64 + i] = S_b[i][j]
__device__ __align__(16) float d_SEG[NSEG * NP * NP];
__device__ int d_segdone = 0;   // segments completed   (reset by block 0)
__device__ int d_flag    = 0;   // R ready              (reset by last gemm block)
__device__ int d_done    = 0;   // gemm blocks past spin (self-resetting)

// ---------------------------------------------------------------------------
// helpers
// ---------------------------------------------------------------------------
__device__ __forceinline__ void cpa16(void* smem, const void* g) {
    unsigned s = (unsigned)__cvta_generic_to_shared(smem);
    asm volatile("cp.async.cg.shared.global [%0], [%1], 16;\n" :: "r"(s), "l"(g));
}
__device__ __forceinline__ void cpa_commit() {
    asm volatile("cp.async.commit_group;\n");
}
template <int N>
__device__ __forceinline__ void cpa_wait() {
    asm volatile("cp.async.wait_group %0;\n" :: "n"(N));
}
__device__ __forceinline__ void fma2(u64& d, u64 a, u64 b) {
    asm("fma.rn.f32x2 %0, %1, %2, %0;" : "+l"(d) : "l"(a), "l"(b));
}
__device__ __forceinline__ u64 dup2(float v) {
    u64 r;
    asm("mov.b64 %0, {%1, %1};" : "=l"(r) : "r"(__float_as_uint(v)));
    return r;
}

// ---------------------------------------------------------------------------
// ONE fused kernel.
//   blocks 0..7   : build segment products S_b (252 rotations, parallel)
//   block  0      : afterwards combines S_7*...*S_0, scales by mus -> d_RT
//   blocks 8..    : cp.async X prologue, brief LOAD-poll on d_flag, then GEMM
// ---------------------------------------------------------------------------
__global__ void __launch_bounds__(256, 2)
fused_kernel(const float* __restrict__ X,
             const float* __restrict__ angles,
             const float* __restrict__ mus,
             float* __restrict__ out) {
    __shared__ __align__(16) u64   sR[NP * NP];          // 32 KB
    __shared__ __align__(16) float sX[2][KCH * BCOLS];   // 32 KB

    const int tid = threadIdx.x;

    // =======================================================================
    // Builder blocks
    // =======================================================================
    if (blockIdx.x < NSEG) {
        const int b = blockIdx.x;
        float2* cs = (float2*)sR;            // 252*8B, aliased
        float*  M  = (float*)sX;             // 65*64*4B, aliased

        for (int t = tid; t < SEGL; t += 256) {
            float s, c;
            sincosf(angles[b * SEGL + t], &s, &c);
            cs[t] = make_float2(c, s);
        }
        if (tid < NP) {
            #pragma unroll
            for (int i = 0; i < NP + 1; i++)
                M[i * NP + tid] = (i == tid) ? 1.0f : 0.0f;
        }
        __syncthreads();

        if (tid < NP) {
            const int j = tid;
            // walker: rotation index b*SEGL -> (it, ib)
            int it = 0, rem = b * SEGL;
            while (rem >= 63 - it) { rem -= 63 - it; it++; }
            int ib = it + 1 + rem;

            float* col = &M[j];
            float vt = col[it * NP];
            float mb = col[ib * NP];
            for (int t = 0; t < SEGL; t++) {
                int itn = it, ibn = ib + 1;
                if (ibn == NP) { itn = it + 1; ibn = itn + 1; }
                const float2 c_s = cs[t];
                const float  mbn = col[ibn * NP];        // row-64 pad-safe
                const float  smb = c_s.y * mb;
                const float  cmb = c_s.x * mb;
                const float  nb  = fmaf(c_s.y, vt, cmb);   // vb' = s*vt + c*vb
                const float  nvt = fmaf(c_s.x, vt, -smb);  // vt' = c*vt - s*vb
                col[ib * NP] = nb;
                if (itn != it) {                         // sweep boundary
                    col[it * NP] = nvt;
                    vt = col[itn * NP];
                    mb = col[ibn * NP];
                } else { vt = nvt; mb = mbn; }
                it = itn; ib = ibn;
            }
            col[it * NP] = vt;
        }
        __syncthreads();
        if (tid < NP) {                      // column-major S_b
            float* Sg = d_SEG + b * (NP * NP) + tid * NP;
            for (int i = 0; i < NP; i++) Sg[i] = M[i * NP + tid];
        }
        __syncthreads();
        if (tid == 0) {
            __threadfence();
            atomicAdd(&d_segdone, 1);
        }
        if (b != 0) return;

        // ---- block 0: combine P = S7 * ... * S0 ----
        if (tid == 0) {
            const volatile int* sd = &d_segdone;
            while (*sd < NSEG) __nanosleep(64);
            __threadfence();
        }
        __syncthreads();

        float* P = (float*)sR;               // P[2][4096], 32 KB, aliased
        const int j = tid & 63;
        const int q = tid >> 6;
        for (int t = tid; t < NP * NP; t += 256) P[t] = d_SEG[t];
        __syncthreads();

        int cur = 0;
        for (int s = 1; s < NSEG; s++) {
            const float* Sg = d_SEG + s * (NP * NP);
            const float* Pc = &P[cur * (NP * NP) + j * NP];
            float acc[16];
            #pragma unroll
            for (int i = 0; i < 16; i++) acc[i] = 0.0f;
            for (int k = 0; k < NP; k++) {
                const float bv = Pc[k];
                const float4* A4 = (const float4*)(Sg + k * NP + q * 16);
                const float4 a0 = A4[0], a1 = A4[1], a2 = A4[2], a3 = A4[3];
                acc[ 0] = fmaf(a0.x, bv, acc[ 0]);
                acc[ 1] = fmaf(a0.y, bv, acc[ 1]);
                acc[ 2] = fmaf(a0.z, bv, acc[ 2]);
                acc[ 3] = fmaf(a0.w, bv, acc[ 3]);
                acc[ 4] = fmaf(a1.x, bv, acc[ 4]);
                acc[ 5] = fmaf(a1.y, bv, acc[ 5]);
                acc[ 6] = fmaf(a1.z, bv, acc[ 6]);
                acc[ 7] = fmaf(a1.w, bv, acc[ 7]);
                acc[ 8] = fmaf(a2.x, bv, acc[ 8]);
                acc[ 9] = fmaf(a2.y, bv, acc[ 9]);
                acc[10] = fmaf(a2.z, bv, acc[10]);
                acc[11] = fmaf(a2.w, bv, acc[11]);
                acc[12] = fmaf(a3.x, bv, acc[12]);
                acc[13] = fmaf(a3.y, bv, acc[13]);
                acc[14] = fmaf(a3.z, bv, acc[14]);
                acc[15] = fmaf(a3.w, bv, acc[15]);
            }
            float* Pd = &P[(cur ^ 1) * (NP * NP) + j * NP + q * 16];
            #pragma unroll
            for (int i = 0; i < 16; i++) Pd[i] = acc[i];
            __syncthreads();
            cur ^= 1;
        }
        // d_RT[k*64+i] = P[i][k]*mus[i]  (column-major P: slot k*64+i)
        for (int t = tid; t < NP * NP; t += 256)
            d_RT[t] = P[cur * (NP * NP) + t] * mus[t & 63];
        __syncthreads();
        if (tid == 0) {
            d_segdone = 0;                   // restore launch invariants
            __threadfence();                 // release RT (+ reset)
            atomicExch(&d_flag, 1);
        }
        return;
    }

    // =======================================================================
    // GEMM blocks (proven 100.35us loop)
    // =======================================================================
    const int lane = tid & 31;
    const int wid  = tid >> 5;
    const int col0 = (blockIdx.x - NSEG) * BCOLS;

    const int lrow = tid >> 4;                 // 0..15
    const int gcol = col0 + (tid & 15) * 16;
    const int c0 = min(gcol +  0, NCOLS - 4);
    const int c1 = min(gcol +  4, NCOLS - 4);
    const int c2 = min(gcol +  8, NCOLS - 4);
    const int c3 = min(gcol + 12, NCOLS - 4);
    float* sdst0 = &sX[0][lrow * BCOLS + (tid & 15) * 16];
    float* sdst1 = &sX[1][lrow * BCOLS + (tid & 15) * 16];

    {   // prefetch chunks 0 and 1 (independent of R)
        size_t ro = (size_t)lrow * NCOLS;
        cpa16(sdst0 +  0, X + ro + c0);  cpa16(sdst0 +  4, X + ro + c1);
        cpa16(sdst0 +  8, X + ro + c2);  cpa16(sdst0 + 12, X + ro + c3);
        cpa_commit();
        ro += (size_t)KCH * NCOLS;
        cpa16(sdst1 +  0, X + ro + c0);  cpa16(sdst1 +  4, X + ro + c1);
        cpa16(sdst1 +  8, X + ro + c2);  cpa16(sdst1 + 12, X + ro + c3);
        cpa_commit();
    }

    // wait for R: cheap L2 LOAD polling (no same-address atomic storm)
    if (tid == 0) {
        const volatile int* f = &d_flag;
        if (*f == 0) {
            int backoff = 64;
            do {
                __nanosleep(backoff);
                if (backoff < 2048) backoff <<= 1;
            } while (*f == 0);
        }
        __threadfence();                     // acquire
        if (atomicAdd(&d_done, 1) == NB - 1) {   // last gemm block past spin
            d_done = 0;
            d_flag = 0;
        }
    }
    __syncthreads();

    // stage R as duplicated (v,v) u64 pairs
    const float4* R4 = (const float4*)d_RT;
    for (int t = tid; t < NP * NP / 4; t += 256) {
        float4 v = R4[t];
        sR[t * 4 + 0] = dup2(v.x);
        sR[t * 4 + 1] = dup2(v.y);
        sR[t * 4 + 2] = dup2(v.z);
        sR[t * 4 + 3] = dup2(v.w);
    }

    u64 aA[8][2], aB[8][2];
    #pragma unroll
    for (int il = 0; il < 8; il++) {
        aA[il][0] = aA[il][1] = 0ULL;
        aB[il][0] = aB[il][1] = 0ULL;
    }

    const int rbase = wid * 4;

    #pragma unroll 1
    for (int ch = 0; ch < NCH; ch++) {
        if (ch == NCH - 1) cpa_wait<0>(); else cpa_wait<1>();
        __syncthreads();

        const ulonglong2* xc  = (const ulonglong2*)&sX[ch & 1][0];
        const ulonglong2* sR2 = (const ulonglong2*)sR;
        #pragma unroll
        for (int k = 0; k < KCH; k++) {
            const ulonglong2 cA = xc[k * (BCOLS / 4) + lane];
            const ulonglong2 cB = xc[k * (BCOLS / 4) + lane + 32];
            ulonglong2 rv[4];
            #pragma unroll
            for (int u = 0; u < 4; u++)
                rv[u] = sR2[(ch * KCH + k) * 32 + rbase + u];
            #pragma unroll
            for (int il = 0; il < 8; il++) {
                const u64 Rd = (il & 1) ? rv[il >> 1].y : rv[il >> 1].x;
                fma2(aA[il][0], Rd, cA.x);
                fma2(aA[il][1], Rd, cA.y);
                fma2(aB[il][0], Rd, cB.x);
                fma2(aB[il][1], Rd, cB.y);
            }
        }
        __syncthreads();

        if (ch + 2 < NCH) {
            size_t ro = (size_t)(lrow + (ch + 2) * KCH) * NCOLS;
            float* d = (ch & 1) ? sdst1 : sdst0;
            cpa16(d +  0, X + ro + c0);  cpa16(d +  4, X + ro + c1);
            cpa16(d +  8, X + ro + c2);  cpa16(d + 12, X + ro + c3);
        }
        cpa_commit();
    }

    const int colA = col0 + lane * 4;
    const int colB = colA + 128;
    #pragma unroll
    for (int il = 0; il < 8; il++) {
        const int i = wid * 8 + il;
        if (colA < NCOLS) {
            ulonglong2 v; v.x = aA[il][0]; v.y = aA[il][1];
            *(ulonglong2*)(out + (size_t)i * NCOLS + colA) = v;
        }
        if (colB < NCOLS) {
            ulonglong2 v; v.x = aB[il][0]; v.y = aB[il][1];
            *(ulonglong2*)(out + (size_t)i * NCOLS + colB) = v;
        }
    }
}

// ---------------------------------------------------------------------------
extern "C" void kernel_launch(void* const* d_in, const int* in_sizes, int n_in,
                              void* d_out, int out_size) {
    const float* X      = (const float*)d_in[0];
    const float* angles = (const float*)d_in[1];
    const float* mus    = (const float*)d_in[2];
    float*       out    = (float*)d_out;

    fused_kernel<<<NB + NSEG, 256>>>(X, angles, mus, out);
}

// round 11
// speedup vs baseline: 1.2374x; 1.2374x over previous
#include <cuda_runtime.h>

typedef unsigned long long u64;

#define NP 64
#define NCOLS 500000
#define BCOLS 256
#define NB    ((NCOLS + BCOLS - 1) / BCOLS)   /* 1954 gemm blocks */
#define NANG 2016
#define NSEG  8
#define SEGL  (NANG / NSEG)                   /* 252 rotations per segment */
#define KCH   16                              /* K rows per staged chunk */
#define NCH   (NP / KCH)                      /* 4 chunks */

// RT[k*64 + i] = mus[i] * R[i][k]
__device__ float d_RT[NP * NP];
// segment products, ROW-major: d_SEG[b*4096 + i*64 + j] = S_b[i][j]
__device__ __align__(16) float d_SEG[NSEG * NP * NP];
__device__ int d_segdone = 0;   // segments 1..7 completed (reset by block 0)
__device__ int d_flag    = 0;   // R ready (reset by last gemm block)
__device__ int d_done    = 0;   // gemm blocks past spin (self-resetting)

// ---------------------------------------------------------------------------
// helpers
// ---------------------------------------------------------------------------
__device__ __forceinline__ void cpa16(void* smem, const void* g) {
    unsigned s = (unsigned)__cvta_generic_to_shared(smem);
    asm volatile("cp.async.cg.shared.global [%0], [%1], 16;\n" :: "r"(s), "l"(g));
}
__device__ __forceinline__ void cpa_commit() {
    asm volatile("cp.async.commit_group;\n");
}
template <int N>
__device__ __forceinline__ void cpa_wait() {
    asm volatile("cp.async.wait_group %0;\n" :: "n"(N));
}
__device__ __forceinline__ void fma2(u64& d, u64 a, u64 b) {
    asm("fma.rn.f32x2 %0, %1, %2, %0;" : "+l"(d) : "l"(a), "l"(b));
}
__device__ __forceinline__ u64 dup2(float v) {
    u64 r;
    asm("mov.b64 %0, {%1, %1};" : "=l"(r) : "r"(__float_as_uint(v)));
    return r;
}

// ---------------------------------------------------------------------------
// ONE fused kernel.
//   blocks 0..7 : build segment products S_b (252 rotations, parallel)
//   block  0    : combines S_7*...*S_0 (smem-staged, conflict-free) -> d_RT
//   blocks 8..  : cp.async X prologue, brief poll on d_flag, then GEMM
// ---------------------------------------------------------------------------
__global__ void __launch_bounds__(256, 2)
fused_kernel(const float* __restrict__ X,
             const float* __restrict__ angles,
             const float* __restrict__ mus,
             float* __restrict__ out) {
    __shared__ __align__(16) u64   sR[NP * NP];          // 32 KB
    __shared__ __align__(16) float sX[2][KCH * BCOLS];   // 32 KB

    const int tid = threadIdx.x;

    // =======================================================================
    // Builder blocks
    // =======================================================================
    if (blockIdx.x < NSEG) {
        const int b = blockIdx.x;
        float2* cs = (float2*)sR;            // 252*8B (aliased in sR)
        float*  M  = (float*)sX;             // 65*64 floats, ROW-major (aliased)

        for (int t = tid; t < SEGL; t += 256) {
            float s, c;
            sincosf(angles[b * SEGL + t], &s, &c);
            cs[t] = make_float2(c, s);
        }
        if (tid < NP) {
            #pragma unroll
            for (int i = 0; i < NP + 1; i++)
                M[i * NP + tid] = (i == tid) ? 1.0f : 0.0f;
        }
        __syncthreads();

        if (tid < NP) {
            const int j = tid;
            // walker: rotation index b*SEGL -> (it, ib)
            int it = 0, rem = b * SEGL;
            while (rem >= 63 - it) { rem -= 63 - it; it++; }
            int ib = it + 1 + rem;

            float* col = &M[j];
            float vt = col[it * NP];
            float mb = col[ib * NP];
            for (int t = 0; t < SEGL; t++) {
                int itn = it, ibn = ib + 1;
                if (ibn == NP) { itn = it + 1; ibn = itn + 1; }
                const float2 c_s = cs[t];
                const float  mbn = col[ibn * NP];        // row-64 pad-safe
                const float  smb = c_s.y * mb;
                const float  cmb = c_s.x * mb;
                const float  nb  = fmaf(c_s.y, vt, cmb);   // vb' = s*vt + c*vb
                const float  nvt = fmaf(c_s.x, vt, -smb);  // vt' = c*vt - s*vb
                col[ib * NP] = nb;
                if (itn != it) {                         // sweep boundary
                    col[it * NP] = nvt;
                    vt = col[itn * NP];
                    mb = col[ibn * NP];
                } else { vt = nvt; mb = mbn; }
                it = itn; ib = ibn;
            }
            col[it * NP] = vt;
        }
        __syncthreads();

        if (b != 0) {
            // write S_b ROW-major, coalesced (thread j writes column j entries)
            if (tid < NP) {
                float* Sg = d_SEG + b * (NP * NP);
                for (int i = 0; i < NP; i++)
                    Sg[i * NP + tid] = M[i * NP + tid];
            }
            __syncthreads();
            if (tid == 0) {
                __threadfence();
                atomicAdd(&d_segdone, 1);
            }
            return;
        }

        // ---- block 0: P starts as S0 (already in sX, row-major). Combine. ----
        if (tid == 0) {
            const volatile int* sd = &d_segdone;
            while (*sd < NSEG - 1) __nanosleep(64);
            __threadfence();
        }
        __syncthreads();

        float* P   = (float*)sX;             // P[2][4096]; P0 = M rows 0..63
        float* Ssm = (float*)sR;             // 16 KB stage (cs dead now)
        const int j = tid & 63;
        const int q = tid >> 6;

        int cur = 0;
        for (int s = 1; s < NSEG; s++) {
            // stage S_s (row-major) into smem, coalesced
            const float4* Sg4 = (const float4*)(d_SEG + s * (NP * NP));
            float4* Ss4 = (float4*)Ssm;
            for (int t = tid; t < NP * NP / 4; t += 256) Ss4[t] = Sg4[t];
            __syncthreads();

            // P_new[i][j] = sum_k S[i][k] * P[k][j]   (all accesses conflict-free)
            const float* Pc = P + cur * (NP * NP);
            float acc[16];
            #pragma unroll
            for (int il = 0; il < 16; il++) acc[il] = 0.0f;
            #pragma unroll 4
            for (int k4 = 0; k4 < 16; k4++) {
                const float bv0 = Pc[(k4 * 4 + 0) * NP + j];
                const float bv1 = Pc[(k4 * 4 + 1) * NP + j];
                const float bv2 = Pc[(k4 * 4 + 2) * NP + j];
                const float bv3 = Pc[(k4 * 4 + 3) * NP + j];
                #pragma unroll
                for (int il = 0; il < 16; il++) {
                    const float4 s4 = *(const float4*)&Ssm[(q * 16 + il) * NP + k4 * 4];
                    acc[il] = fmaf(s4.x, bv0,
                              fmaf(s4.y, bv1,
                              fmaf(s4.z, bv2,
                              fmaf(s4.w, bv3, acc[il]))));
                }
            }
            __syncthreads();                 // P[cur] reads done
            float* Pd = P + (cur ^ 1) * (NP * NP);
            #pragma unroll
            for (int il = 0; il < 16; il++)
                Pd[(q * 16 + il) * NP + j] = acc[il];
            __syncthreads();
            cur ^= 1;
        }
        // d_RT[k*64+i] = P[i][k] * mus[i]   (P row-major)
        const float* Pf = P + cur * (NP * NP);
        for (int t = tid; t < NP * NP; t += 256) {
            const int k = t >> 6, i = t & 63;
            d_RT[t] = Pf[i * NP + k] * mus[i];
        }
        __syncthreads();
        if (tid == 0) {
            d_segdone = 0;                   // restore launch invariants
            __threadfence();                 // release RT (+ reset)
            atomicExch(&d_flag, 1);
        }
        return;
    }

    // =======================================================================
    // GEMM blocks (proven 100.35us loop)
    // =======================================================================
    const int lane = tid & 31;
    const int wid  = tid >> 5;
    const int col0 = (blockIdx.x - NSEG) * BCOLS;

    const int lrow = tid >> 4;                 // 0..15
    const int gcol = col0 + (tid & 15) * 16;
    const int c0 = min(gcol +  0, NCOLS - 4);
    const int c1 = min(gcol +  4, NCOLS - 4);
    const int c2 = min(gcol +  8, NCOLS - 4);
    const int c3 = min(gcol + 12, NCOLS - 4);
    float* sdst0 = &sX[0][lrow * BCOLS + (tid & 15) * 16];
    float* sdst1 = &sX[1][lrow * BCOLS + (tid & 15) * 16];

    {   // prefetch chunks 0 and 1 (independent of R)
        size_t ro = (size_t)lrow * NCOLS;
        cpa16(sdst0 +  0, X + ro + c0);  cpa16(sdst0 +  4, X + ro + c1);
        cpa16(sdst0 +  8, X + ro + c2);  cpa16(sdst0 + 12, X + ro + c3);
        cpa_commit();
        ro += (size_t)KCH * NCOLS;
        cpa16(sdst1 +  0, X + ro + c0);  cpa16(sdst1 +  4, X + ro + c1);
        cpa16(sdst1 +  8, X + ro + c2);  cpa16(sdst1 + 12, X + ro + c3);
        cpa_commit();
    }

    // wait for R (overlaps the DRAM prologue above)
    if (tid == 0) {
        const volatile int* f = &d_flag;
        while (*f == 0) __nanosleep(256);
        __threadfence();                     // acquire
        if (atomicAdd(&d_done, 1) == NB - 1) {   // last gemm block past spin
            d_done = 0;
            d_flag = 0;
        }
    }
    __syncthreads();

    // stage R as duplicated (v,v) u64 pairs
    const float4* R4 = (const float4*)d_RT;
    for (int t = tid; t < NP * NP / 4; t += 256) {
        float4 v = R4[t];
        sR[t * 4 + 0] = dup2(v.x);
        sR[t * 4 + 1] = dup2(v.y);
        sR[t * 4 + 2] = dup2(v.z);
        sR[t * 4 + 3] = dup2(v.w);
    }

    u64 aA[8][2], aB[8][2];
    #pragma unroll
    for (int il = 0; il < 8; il++) {
        aA[il][0] = aA[il][1] = 0ULL;
        aB[il][0] = aB[il][1] = 0ULL;
    }

    const int rbase = wid * 4;

    #pragma unroll 1
    for (int ch = 0; ch < NCH; ch++) {
        if (ch == NCH - 1) cpa_wait<0>(); else cpa_wait<1>();
        __syncthreads();

        const ulonglong2* xc  = (const ulonglong2*)&sX[ch & 1][0];
        const ulonglong2* sR2 = (const ulonglong2*)sR;
        #pragma unroll
        for (int k = 0; k < KCH; k++) {
            const ulonglong2 cA = xc[k * (BCOLS / 4) + lane];
            const ulonglong2 cB = xc[k * (BCOLS / 4) + lane + 32];
            ulonglong2 rv[4];
            #pragma unroll
            for (int u = 0; u < 4; u++)
                rv[u] = sR2[(ch * KCH + k) * 32 + rbase + u];
            #pragma unroll
            for (int il = 0; il < 8; il++) {
                const u64 Rd = (il & 1) ? rv[il >> 1].y : rv[il >> 1].x;
                fma2(aA[il][0], Rd, cA.x);
                fma2(aA[il][1], Rd, cA.y);
                fma2(aB[il][0], Rd, cB.x);
                fma2(aB[il][1], Rd, cB.y);
            }
        }
        __syncthreads();

        if (ch + 2 < NCH) {
            size_t ro = (size_t)(lrow + (ch + 2) * KCH) * NCOLS;
            float* d = (ch & 1) ? sdst1 : sdst0;
            cpa16(d +  0, X + ro + c0);  cpa16(d +  4, X + ro + c1);
            cpa16(d +  8, X + ro + c2);  cpa16(d + 12, X + ro + c3);
        }
        cpa_commit();
    }

    const int colA = col0 + lane * 4;
    const int colB = colA + 128;
    #pragma unroll
    for (int il = 0; il < 8; il++) {
        const int i = wid * 8 + il;
        if (colA < NCOLS) {
            ulonglong2 v; v.x = aA[il][0]; v.y = aA[il][1];
            *(ulonglong2*)(out + (size_t)i * NCOLS + colA) = v;
        }
        if (colB < NCOLS) {
            ulonglong2 v; v.x = aB[il][0]; v.y = aB[il][1];
            *(ulonglong2*)(out + (size_t)i * NCOLS + colB) = v;
        }
    }
}

// ---------------------------------------------------------------------------
extern "C" void kernel_launch(void* const* d_in, const int* in_sizes, int n_in,
                              void* d_out, int out_size) {
    const float* X      = (const float*)d_in[0];
    const float* angles = (const float*)d_in[1];
    const float* mus    = (const float*)d_in[2];
    float*       out    = (float*)d_out;

    fused_kernel<<<NB + NSEG, 256>>>(X, angles, mus, out);
}

// round 13
// speedup vs baseline: 1.8785x; 1.5181x over previous
#include <cuda_runtime.h>
#include <cuda_bf16.h>
#include <cstdint>

#define NP    64
#define NCOLS 500000
#define NT    128                       /* columns per gemm tile */
#define NB    ((NCOLS + NT - 1) / NT)   /* 3907 gemm blocks */
#define NANG  2016
#define NSEG  8
#define SEGL  (NANG / NSEG)             /* 252 */
#define XPITCH 132                      /* padded X row pitch (floats) */
#define RPITCH 36                       /* padded R row pitch (u32 pair-words) */
#define DYN_BYTES 53248

// R split into bf16 hi/lo pair-words: d_Rh[n*32+k2] = {bf16 Rs[n][2k2] (lo), bf16 Rs[n][2k2+1] (hi)}
__device__ uint32_t d_Rh[NP * 32];
__device__ uint32_t d_Rl[NP * 32];
// segment products, ROW-major: d_SEG[b*4096 + i*64 + j] = S_b[i][j]
__device__ __align__(16) float d_SEG[NSEG * NP * NP];
__device__ int d_segdone = 0;
__device__ int d_flag    = 0;
__device__ int d_done    = 0;

// ---------------------------------------------------------------------------
// helpers
// ---------------------------------------------------------------------------
__device__ __forceinline__ void cpa16(uint32_t smem, const void* g) {
    asm volatile("cp.async.cg.shared.global [%0], [%1], 16;\n" :: "r"(smem), "l"(g));
}
__device__ __forceinline__ void cpa_commit() { asm volatile("cp.async.commit_group;\n"); }
template <int N> __device__ __forceinline__ void cpa_wait() {
    asm volatile("cp.async.wait_group %0;\n" :: "n"(N));
}
__device__ __forceinline__ uint32_t smem_u32(const void* p) {
    uint32_t a;
    asm("{ .reg .u64 t; cvta.to.shared.u64 t, %1; cvt.u32.u64 %0, t; }" : "=r"(a) : "l"(p));
    return a;
}
// split (x0,x1) into bf16x2 hi word + bf16x2 residual word (x0 in low half)
__device__ __forceinline__ void bsplit(float x0, float x1, uint32_t& hi, uint32_t& lo) {
    __nv_bfloat162 h = __floats2bfloat162_rn(x0, x1);       // .x = x0 (low)
    hi = *reinterpret_cast<uint32_t*>(&h);
    __nv_bfloat162 l = __floats2bfloat162_rn(x0 - __bfloat162float(h.x),
                                             x1 - __bfloat162float(h.y));
    lo = *reinterpret_cast<uint32_t*>(&l);
}
__device__ __forceinline__ uint32_t bf2_bits(__nv_bfloat16 a, __nv_bfloat16 b) {
    __nv_bfloat162 h = __halves2bfloat162(a, b);            // a = low half
    return *reinterpret_cast<uint32_t*>(&h);
}
// warp MMA: D(16x8,f32) += A(16x16,bf16,row) * B(16x8,bf16,col)
__device__ __forceinline__ void mma16816(float* c, const uint32_t* a, const uint32_t* b) {
    asm volatile("mma.sync.aligned.m16n8k16.row.col.f32.bf16.bf16.f32 "
        "{%0,%1,%2,%3}, {%4,%5,%6,%7}, {%8,%9}, {%0,%1,%2,%3};"
        : "+f"(c[0]), "+f"(c[1]), "+f"(c[2]), "+f"(c[3])
        : "r"(a[0]), "r"(a[1]), "r"(a[2]), "r"(a[3]), "r"(b[0]), "r"(b[1]));
}

// ---------------------------------------------------------------------------
// ONE fused kernel, 128 threads/block.
//   blocks 0..7 : segment products (parallel);  block 0: combine -> d_Rh/d_Rl
//   blocks 8..  : warp-MMA bf16 hi/lo split GEMM tile (128 cols x 64 rows)
// ---------------------------------------------------------------------------
__global__ void __launch_bounds__(128, 4)
fused_kernel(const float* __restrict__ X,
             const float* __restrict__ angles,
             const float* __restrict__ mus,
             float* __restrict__ out) {
    extern __shared__ __align__(16) char dsm[];
    const uint32_t base = smem_u32(dsm);
    const int tid = threadIdx.x;

    // =======================================================================
    // Builder blocks (proven path from R11/R12)
    // =======================================================================
    if (blockIdx.x < NSEG) {
        const int b = blockIdx.x;
        float2* cs = (float2*)dsm;                       // 252*8 B
        float*  M  = (float*)(dsm + 2048);               // 65 rows x 64 f

        for (int t = tid; t < SEGL; t += 128) {
            float s, c;
            sincosf(angles[b * SEGL + t], &s, &c);
            cs[t] = make_float2(c, s);
        }
        if (tid < NP) {
            #pragma unroll
            for (int i = 0; i < NP + 1; i++)
                M[i * NP + tid] = (i == tid) ? 1.0f : 0.0f;
        }
        __syncthreads();

        if (tid < NP) {
            const int j = tid;
            int it = 0, rem = b * SEGL;
            while (rem >= 63 - it) { rem -= 63 - it; it++; }
            int ib = it + 1 + rem;

            float* col = &M[j];
            float vt = col[it * NP];
            float mb = col[ib * NP];
            for (int t = 0; t < SEGL; t++) {
                int itn = it, ibn = ib + 1;
                if (ibn == NP) { itn = it + 1; ibn = itn + 1; }
                const float2 c_s = cs[t];
                const float  mbn = col[ibn * NP];
                const float  smb = c_s.y * mb;
                const float  cmb = c_s.x * mb;
                const float  nb  = fmaf(c_s.y, vt, cmb);
                const float  nvt = fmaf(c_s.x, vt, -smb);
                col[ib * NP] = nb;
                if (itn != it) {
                    col[it * NP] = nvt;
                    vt = col[itn * NP];
                    mb = col[ibn * NP];
                } else { vt = nvt; mb = mbn; }
                it = itn; ib = ibn;
            }
            col[it * NP] = vt;
        }
        __syncthreads();

        if (b != 0) {
            if (tid < NP) {
                float* Sg = d_SEG + b * (NP * NP);
                for (int i = 0; i < NP; i++)
                    Sg[i * NP + tid] = M[i * NP + tid];
            }
            __syncthreads();
            if (tid == 0) { __threadfence(); atomicAdd(&d_segdone, 1); }
            return;
        }

        // ---- block 0: combine P = S7*...*S0 (P0 = M rows 0..63 in place) ----
        if (tid == 0) {
            const volatile int* sd = &d_segdone;
            while (*sd < NSEG - 1) __nanosleep(64);
            __threadfence();
        }
        __syncthreads();

        float* P0  = (float*)(dsm + 2048);
        float* P1  = (float*)(dsm + 18432);
        float* Ssm = (float*)(dsm + 36864);
        const int j = tid & 63;
        const int q = tid >> 6;                          // 0..1, 32 rows each

        float* Pc = P0; float* Pd = P1;
        for (int s = 1; s < NSEG; s++) {
            const float4* Sg4 = (const float4*)(d_SEG + s * (NP * NP));
            float4* Ss4 = (float4*)Ssm;
            for (int t = tid; t < NP * NP / 4; t += 128) Ss4[t] = Sg4[t];
            __syncthreads();

            float acc[32];
            #pragma unroll
            for (int il = 0; il < 32; il++) acc[il] = 0.0f;
            #pragma unroll 4
            for (int k4 = 0; k4 < 16; k4++) {
                const float bv0 = Pc[(k4 * 4 + 0) * NP + j];
                const float bv1 = Pc[(k4 * 4 + 1) * NP + j];
                const float bv2 = Pc[(k4 * 4 + 2) * NP + j];
                const float bv3 = Pc[(k4 * 4 + 3) * NP + j];
                #pragma unroll
                for (int il = 0; il < 32; il++) {
                    const float4 s4 = *(const float4*)&Ssm[(q * 32 + il) * NP + k4 * 4];
                    acc[il] = fmaf(s4.x, bv0, fmaf(s4.y, bv1,
                              fmaf(s4.z, bv2, fmaf(s4.w, bv3, acc[il]))));
                }
            }
            __syncthreads();
            #pragma unroll
            for (int il = 0; il < 32; il++)
                Pd[(q * 32 + il) * NP + j] = acc[il];
            __syncthreads();
            float* tmp = Pc; Pc = Pd; Pd = tmp;
        }
        // split Rs[n][k] = Pc[n*64+k]*mus[n] into bf16 hi/lo pair-words
        for (int t = tid; t < NP * 32; t += 128) {
            const int n = t >> 5, k2 = t & 31;
            const float m = mus[n];
            const float v0 = Pc[n * NP + 2 * k2]     * m;
            const float v1 = Pc[n * NP + 2 * k2 + 1] * m;
            const __nv_bfloat16 h0 = __float2bfloat16(v0);
            const __nv_bfloat16 h1 = __float2bfloat16(v1);
            d_Rh[t] = bf2_bits(h0, h1);
            d_Rl[t] = bf2_bits(__float2bfloat16(v0 - __bfloat162float(h0)),
                               __float2bfloat16(v1 - __bfloat162float(h1)));
        }
        __syncthreads();
        if (tid == 0) {
            d_segdone = 0;
            __threadfence();
            atomicExch(&d_flag, 1);
        }
        return;
    }

    // =======================================================================
    // GEMM blocks: warp-MMA tile of NT=128 columns x 64 rows
    // =======================================================================
    float*    sXf = (float*)dsm;                          // [64][132] fp32, 33792 B
    uint32_t* sRh = (uint32_t*)(dsm + 33792);             // [64][36] pair-words
    uint32_t* sRl = (uint32_t*)(dsm + 43008);

    const int col0 = (blockIdx.x - NSEG) * NT;

    // 1. stage X tile via cp.async (independent of R); padded pitch 132 floats
    #pragma unroll
    for (int p = 0; p < 16; p++) {
        const int idx = p * 128 + tid;
        const int row = idx >> 5, seg = idx & 31;
        const int c   = min(col0 + seg * 4, NCOLS - 4);
        cpa16(base + (row * XPITCH + seg * 4) * 4, X + (size_t)row * NCOLS + c);
    }
    cpa_commit();

    // 2. wait for R (overlaps the DRAM prologue)
    if (tid == 0) {
        const volatile int* f = &d_flag;
        while (*f == 0) __nanosleep(256);
        __threadfence();
        if (atomicAdd(&d_done, 1) == NB - 1) { d_done = 0; d_flag = 0; }
    }
    __syncthreads();

    // 3. stage R pair-words (padded pitch 36)
    #pragma unroll
    for (int p = 0; p < 16; p++) {
        const int t = p * 128 + tid;                 // 0..2047
        const int n = t >> 5, k2 = t & 31;
        sRh[n * RPITCH + k2] = d_Rh[t];
        sRl[n * RPITCH + k2] = d_Rl[t];
    }
    cpa_wait<0>();
    __syncthreads();

    // 4. warp-MMA: warp w -> output columns col0 + w*32 .. +31
    const int w  = tid >> 5;
    const int l  = tid & 31;
    const int lq = l >> 2;                           // l/4
    const int lr = l & 3;                            // l%4

    float acc[2][8][4];
    #pragma unroll
    for (int mf = 0; mf < 2; mf++)
        #pragma unroll
        for (int nf = 0; nf < 8; nf++)
            #pragma unroll
            for (int r = 0; r < 4; r++) acc[mf][nf][r] = 0.0f;

    #pragma unroll
    for (int kc = 0; kc < 4; kc++) {
        // A fragments (hi+lo) converted from fp32 smem
        uint32_t ahi[2][4], alo[2][4];
        #pragma unroll
        for (int mf = 0; mf < 2; mf++) {
            const int m0 = w * 32 + mf * 16 + lq;    // rows of A = X columns
            #pragma unroll
            for (int half = 0; half < 2; half++) {
                const int k2 = kc * 8 + lr + half * 4;
                const float* r0 = &sXf[(2 * k2) * XPITCH];
                const float* r1 = &sXf[(2 * k2 + 1) * XPITCH];
                bsplit(r0[m0],     r1[m0],     ahi[mf][half * 2 + 0], alo[mf][half * 2 + 0]);
                bsplit(r0[m0 + 8], r1[m0 + 8], ahi[mf][half * 2 + 1], alo[mf][half * 2 + 1]);
            }
        }
        // B fragments in two groups of 4 nf (register pressure)
        #pragma unroll
        for (int nh = 0; nh < 2; nh++) {
            uint32_t bh[4][2], bl[4][2];
            #pragma unroll
            for (int nfi = 0; nfi < 4; nfi++) {
                const int n   = (nh * 4 + nfi) * 8 + lq;
                const int i0  = n * RPITCH + kc * 8 + lr;
                bh[nfi][0] = sRh[i0];     bh[nfi][1] = sRh[i0 + 4];
                bl[nfi][0] = sRl[i0];     bl[nfi][1] = sRl[i0 + 4];
            }
            #pragma unroll
            for (int mf = 0; mf < 2; mf++)
                #pragma unroll
                for (int nfi = 0; nfi < 4; nfi++) {
                    float* c = acc[mf][nh * 4 + nfi];
                    mma16816(c, ahi[mf], bh[nfi]);   // hi*hi
                    mma16816(c, ahi[mf], bl[nfi]);   // hi*lo
                    mma16816(c, alo[mf], bh[nfi]);   // lo*hi
                }
        }
    }

    // 5. store: c0/c1 -> (mA, n0/n0+1); c2/c3 -> (mA+8, n0/n0+1)
    #pragma unroll
    for (int mf = 0; mf < 2; mf++) {
        const int mA = w * 32 + mf * 16 + lq;
        const int mB = mA + 8;
        const bool okA = (col0 + mA < NCOLS);
        const bool okB = (col0 + mB < NCOLS);
        float* opA = out + col0 + mA;
        float* opB = out + col0 + mB;
        #pragma unroll
        for (int nf = 0; nf < 8; nf++) {
            const int n0 = nf * 8 + lr * 2;
            const float* c = acc[mf][nf];
            if (okA) {
                opA[(size_t)n0 * NCOLS]       = c[0];
                opA[(size_t)(n0 + 1) * NCOLS] = c[1];
            }
            if (okB) {
                opB[(size_t)n0 * NCOLS]       = c[2];
                opB[(size_t)(n0 + 1) * NCOLS] = c[3];
            }
        }
    }
}

// ---------------------------------------------------------------------------
extern "C" void kernel_launch(void* const* d_in, const int* in_sizes, int n_in,
                              void* d_out, int out_size) {
    const float* X      = (const float*)d_in[0];
    const float* angles = (const float*)d_in[1];
    const float* mus    = (const float*)d_in[2];
    float*       out    = (float*)d_out;

    cudaFuncSetAttribute(fused_kernel,
                         cudaFuncAttributeMaxDynamicSharedMemorySize, DYN_BYTES);
    fused_kernel<<<NB + NSEG, 128, DYN_BYTES>>>(X, angles, mus, out);
}